// round 14
// baseline (speedup 1.0000x reference)
#include <cuda_runtime.h>
#include <cuda_fp16.h>
#include <cstdint>
#include <cstddef>

#define T_TOK 8192
#define DM    1024
#define NE    8

#define BM 128
#define BN 128                    // N-split: doubles work items, kills tail waste
#define CHUNK 64                  // halves of K per chunk (=128 B/row)
#define NCH (DM/CHUNK)            // 16
#define ABYTES (BM*128)           // 16384 per A stage
#define BBYTES (BN*128)           // 16384 per B stage
#define A_OFF 2048
#define B_OFF (A_OFF + 3*ABYTES)              // 51200
#define SMEM_TOTAL (B_OFF + 3*BBYTES)         // 100352
#define GRID_GEMM 152

// ---- static device scratch (no allocations allowed) ----
__device__ __align__(16) __half g_x_h[(size_t)T_TOK * DM];     // fp16 x
__device__ __align__(16) __half g_We_h[(size_t)NE * DM * DM];  // fp16 We
__device__ int   g_tok[NE * T_TOK];
__device__ float g_wgt[NE * T_TOK];
__device__ int   g_cnt[16];   // [0..7]=counts, [8]=steal counter, [9]=done counter
                              // zero-initialized at load; GEMM self-resets per replay

__device__ __forceinline__ void cp16(uint32_t dst, const void* src) {
    asm volatile("cp.async.cg.shared.global [%0], [%1], 16;" :: "r"(dst), "l"(src) : "memory");
}

// ---- kernel 1: interleaved gate + prep (R11, unchanged) ----
// 5120 blocks: bid%5==0 -> gate (1024 blocks, 8 tokens each);
// others -> prep (4096 blocks, 512 float4s: We->fp16 + zero out).
__global__ void prep_gate_kernel(const float4* __restrict__ We, float4* __restrict__ out,
                                 const float* __restrict__ x, const float* __restrict__ Wg,
                                 const float* __restrict__ bg) {
    const int bid = blockIdx.x;
    const int tid = threadIdx.x;

    if (bid % 5 != 0) {
        int p = (bid / 5) * 4 + (bid % 5 - 1);       // 0..4095
        int i0 = p * 512 + tid;
        float4 w0 = We[i0];
        float4 w1 = We[i0 + 256];
        __half2 a0 = __floats2half2_rn(w0.x, w0.y);
        __half2 a1 = __floats2half2_rn(w0.z, w0.w);
        __half2 b0 = __floats2half2_rn(w1.x, w1.y);
        __half2 b1 = __floats2half2_rn(w1.z, w1.w);
        uint2 pk0, pk1;
        pk0.x = *reinterpret_cast<uint32_t*>(&a0);
        pk0.y = *reinterpret_cast<uint32_t*>(&a1);
        pk1.x = *reinterpret_cast<uint32_t*>(&b0);
        pk1.y = *reinterpret_cast<uint32_t*>(&b1);
        reinterpret_cast<uint2*>(g_We_h)[i0]       = pk0;
        reinterpret_cast<uint2*>(g_We_h)[i0 + 256] = pk1;
        out[i0]       = make_float4(0.f, 0.f, 0.f, 0.f);   // T_TOK*DM == NE*DM*DM
        out[i0 + 256] = make_float4(0.f, 0.f, 0.f, 0.f);
        return;
    }

    int t = (bid / 5) * 8 + (tid >> 5);
    int lane = tid & 31;
    const float4* xr4 = (const float4*)(x + (size_t)t * DM);
    uint2* xh2 = (uint2*)(g_x_h + (size_t)t * DM);

    float acc[NE];
#pragma unroll
    for (int e = 0; e < NE; e++) acc[e] = 0.f;

#pragma unroll
    for (int it = 0; it < DM / 4 / 32; it++) {
        int d4 = it * 32 + lane;
        float4 v = xr4[d4];
        __half2 h0 = __floats2half2_rn(v.x, v.y);
        __half2 h1 = __floats2half2_rn(v.z, v.w);
        uint2 pk;
        pk.x = *reinterpret_cast<uint32_t*>(&h0);
        pk.y = *reinterpret_cast<uint32_t*>(&h1);
        xh2[d4] = pk;
#pragma unroll
        for (int e = 0; e < NE; e++) {
            float4 g = ((const float4*)(Wg + e * DM))[d4];
            acc[e] = fmaf(v.x, g.x, acc[e]);
            acc[e] = fmaf(v.y, g.y, acc[e]);
            acc[e] = fmaf(v.z, g.z, acc[e]);
            acc[e] = fmaf(v.w, g.w, acc[e]);
        }
    }
#pragma unroll
    for (int e = 0; e < NE; e++) {
#pragma unroll
        for (int o = 16; o > 0; o >>= 1) acc[e] += __shfl_xor_sync(0xffffffffu, acc[e], o);
    }

    if (lane == 0) {
        float l[NE];
        float m = -1e30f;
#pragma unroll
        for (int e = 0; e < NE; e++) { l[e] = acc[e] + bg[e]; m = fmaxf(m, l[e]); }
        float p[NE];
        float s = 0.f;
#pragma unroll
        for (int e = 0; e < NE; e++) { p[e] = expf(l[e] - m); s += p[e]; }
        int e0 = 0;
#pragma unroll
        for (int e = 1; e < NE; e++) if (l[e] > l[e0]) e0 = e;
        int e1 = (e0 == 0) ? 1 : 0;
#pragma unroll
        for (int e = 0; e < NE; e++) if (e != e0 && l[e] > l[e1]) e1 = e;
        float inv = 1.f / s;

        int q0 = atomicAdd(&g_cnt[e0], 1);
        g_tok[e0 * T_TOK + q0] = t;
        g_wgt[e0 * T_TOK + q0] = p[e0] * inv;
        int q1 = atomicAdd(&g_cnt[e1], 1);
        g_tok[e1 * T_TOK + q1] = t;
        g_wgt[e1 * T_TOK + q1] = p[e1] * inv;
    }
}

// ---- kernel 2: persistent gathered per-expert fp16 GEMM ----
// CTA tile 128x128, 8 warps (2M x 4N), warp tile 64x32, SW128-swizzled smem,
// 3-stage cp.async pipeline (prefetch under ks=0 MMAs), 1 bar/chunk,
// atomic work-stealing over ~1040 half-tiles (tail waste ~2%).
__global__ void __launch_bounds__(256, 1)
moe_gemm_kernel(const float* __restrict__ be, float* __restrict__ out) {
    extern __shared__ __align__(1024) char sm[];
    int*   s_tok  = (int*)sm;              // 128 ints
    float* s_w    = (float*)(sm + 512);    // 128 floats
    float* s_bias = (float*)(sm + 1024);   // 128 floats
    int*   s_wid  = (int*)(sm + 1536);
    int*   s_cnt  = (int*)(sm + 1552);     // 8 ints

    const int tid = threadIdx.x;
    const uint32_t sbase = (uint32_t)__cvta_generic_to_shared(sm);

    if (tid < 8) s_cnt[tid] = g_cnt[tid];

    const int wid = tid >> 5, lane = tid & 31;
    const int wm = (wid & 1) * 64;        // 2 M-warps
    const int wn = (wid >> 1) * 32;       // 4 N-warps
    const int gid = lane >> 2, tig = lane & 3;
    const uint32_t cmask = (uint32_t)((lane & 7) << 4);

    const uint32_t a_row = (uint32_t)(lane & 15);
    const uint32_t a_chi = (uint32_t)((lane >> 4) << 4);
    const uint32_t b_row = (uint32_t)(((lane >> 4) << 3) + (lane & 7));
    const uint32_t b_chi = (uint32_t)(((lane >> 3) & 1) << 4);

    for (;;) {
        if (tid == 0) *s_wid = atomicAdd(&g_cnt[8], 1);
        __syncthreads();                   // publish s_wid/s_cnt; prev epilogue done
        const int w = *s_wid;

        // map work id -> (e, nb, mb); m innermost (consecutive ids share B tile)
        int rem = w, e = -1, mb = 0, nb = 0;
#pragma unroll
        for (int ee = 0; ee < NE; ee++) {
            int c = s_cnt[ee];
            int mbe = (c + BM - 1) >> 7;
            int it = mbe * (DM / BN);
            if (e < 0) {
                if (rem < it) { e = ee; nb = rem / mbe; mb = rem - nb * mbe; }
                else rem -= it;
            }
        }
        if (e < 0) break;

        const int cnt = s_cnt[e];
        const int m0 = mb * BM;
        const int n0 = nb * BN;

        if (tid < BM) {
            int pos = m0 + tid;
            int tok = 0; float wt = 0.f;
            if (pos < cnt) { tok = g_tok[e * T_TOK + pos]; wt = g_wgt[e * T_TOK + pos]; }
            s_tok[tid] = tok; s_w[tid] = wt;
        } else {
            s_bias[tid - BM] = be[e * DM + n0 + (tid - BM)];
        }
        __syncthreads();

        // cp.async mapping (per chunk): A = 1024 granules (4/thr), B = 1024 (4/thr)
        const __half* a_src[4];
        uint32_t a_dst[4];
#pragma unroll
        for (int i = 0; i < 4; i++) {
            int slot = i * 256 + tid;
            int row = slot >> 3, q = slot & 7;
            a_src[i] = g_x_h + (size_t)s_tok[row] * DM + q * 8;
            a_dst[i] = sbase + A_OFF + (uint32_t)(row * 128 + ((q ^ (row & 7)) << 4));
        }
        const __half* b_src[4];
        uint32_t b_dst[4];
#pragma unroll
        for (int i = 0; i < 4; i++) {
            int slot = i * 256 + tid;
            int row = slot >> 3, q = slot & 7;
            b_src[i] = g_We_h + (size_t)e * DM * DM + (size_t)(n0 + row) * DM + q * 8;
            b_dst[i] = sbase + B_OFF + (uint32_t)(row * 128 + ((q ^ (row & 7)) << 4));
        }

        float acc[4][4][4];
#pragma unroll
        for (int i0 = 0; i0 < 4; i0++)
#pragma unroll
            for (int i1 = 0; i1 < 4; i1++)
#pragma unroll
                for (int i2 = 0; i2 < 4; i2++) acc[i0][i1][i2] = 0.f;

#pragma unroll
        for (int ch = 0; ch < 2; ch++) {
            int k0 = ch * CHUNK;
#pragma unroll
            for (int i = 0; i < 4; i++) cp16(a_dst[i] + ch * ABYTES, a_src[i] + k0);
#pragma unroll
            for (int i = 0; i < 4; i++) cp16(b_dst[i] + ch * BBYTES, b_src[i] + k0);
            asm volatile("cp.async.commit_group;" ::: "memory");
        }

        for (int ch = 0; ch < NCH; ++ch) {
            if (ch < NCH - 1) asm volatile("cp.async.wait_group 1;" ::: "memory");
            else              asm volatile("cp.async.wait_group 0;" ::: "memory");
            __syncthreads();

            const uint32_t Ab = sbase + A_OFF + (ch % 3) * ABYTES;
            const uint32_t Bb = sbase + B_OFF + (ch % 3) * BBYTES;

#pragma unroll
            for (int ks = 0; ks < 4; ks++) {
                uint32_t af[4][4];
#pragma unroll
                for (int ma = 0; ma < 4; ma++) {
                    uint32_t cb = (uint32_t)(ks * 32) + a_chi;
                    uint32_t addr = Ab + (wm + ma * 16 + a_row) * 128 + (cb ^ cmask);
                    asm volatile("ldmatrix.sync.aligned.m8n8.x4.shared.b16 {%0,%1,%2,%3}, [%4];"
                                 : "=r"(af[ma][0]), "=r"(af[ma][1]), "=r"(af[ma][2]), "=r"(af[ma][3])
                                 : "r"(addr));
                }
                uint32_t bf[2][4];
#pragma unroll
                for (int nb2 = 0; nb2 < 2; nb2++) {
                    uint32_t cb = (uint32_t)(ks * 32) + b_chi;
                    uint32_t addr = Bb + (wn + nb2 * 16 + b_row) * 128 + (cb ^ cmask);
                    asm volatile("ldmatrix.sync.aligned.m8n8.x4.shared.b16 {%0,%1,%2,%3}, [%4];"
                                 : "=r"(bf[nb2][0]), "=r"(bf[nb2][1]), "=r"(bf[nb2][2]), "=r"(bf[nb2][3])
                                 : "r"(addr));
                }
#pragma unroll
                for (int ma = 0; ma < 4; ma++)
#pragma unroll
                    for (int na = 0; na < 4; na++) {
                        uint32_t b0 = bf[na >> 1][(na & 1) * 2];
                        uint32_t b1 = bf[na >> 1][(na & 1) * 2 + 1];
                        asm volatile(
                            "mma.sync.aligned.m16n8k16.row.col.f32.f16.f16.f32 "
                            "{%0,%1,%2,%3}, {%4,%5,%6,%7}, {%8,%9}, {%0,%1,%2,%3};"
                            : "+f"(acc[ma][na][0]), "+f"(acc[ma][na][1]),
                              "+f"(acc[ma][na][2]), "+f"(acc[ma][na][3])
                            : "r"(af[ma][0]), "r"(af[ma][1]), "r"(af[ma][2]), "r"(af[ma][3]),
                              "r"(b0), "r"(b1));
                    }

                if (ks == 0 && ch + 2 < NCH) {
                    int st = (ch + 2) % 3;
                    int k0 = (ch + 2) * CHUNK;
#pragma unroll
                    for (int i = 0; i < 4; i++) cp16(a_dst[i] + st * ABYTES, a_src[i] + k0);
#pragma unroll
                    for (int i = 0; i < 4; i++) cp16(b_dst[i] + st * BBYTES, b_src[i] + k0);
                    asm volatile("cp.async.commit_group;" ::: "memory");
                }
            }
        }

        // ---- epilogue: pair-shuffle to 4 consecutive cols, one red.v4 each ----
        const bool odd = (tig & 1);
#pragma unroll
        for (int ma = 0; ma < 4; ma++) {
            int r = wm + ma * 16 + gid;
            int rr = odd ? r + 8 : r;
            int tok = s_tok[rr];
            float wt = s_w[rr];
            float* orow = out + (size_t)tok * DM + n0;
#pragma unroll
            for (int na = 0; na < 4; na++) {
                float v0 = acc[ma][na][0], v1 = acc[ma][na][1];
                float v2 = acc[ma][na][2], v3 = acc[ma][na][3];
                float u0 = __shfl_xor_sync(0xffffffffu, v0, 1);
                float u1 = __shfl_xor_sync(0xffffffffu, v1, 1);
                float u2 = __shfl_xor_sync(0xffffffffu, v2, 1);
                float u3 = __shfl_xor_sync(0xffffffffu, v3, 1);
                float r0, r1, r2, r3;
                if (!odd) { r0 = v0; r1 = v1; r2 = u0; r3 = u1; }
                else      { r0 = u2; r1 = u3; r2 = v2; r3 = v3; }
                int j4 = wn + na * 8 + (tig >> 1) * 4;
                if (wt != 0.f) {
                    float o0 = wt * (r0 + s_bias[j4 + 0]);
                    float o1 = wt * (r1 + s_bias[j4 + 1]);
                    float o2 = wt * (r2 + s_bias[j4 + 2]);
                    float o3 = wt * (r3 + s_bias[j4 + 3]);
                    asm volatile("red.global.add.v4.f32 [%0], {%1,%2,%3,%4};"
                                 :: "l"(orow + j4), "f"(o0), "f"(o1), "f"(o2), "f"(o3)
                                 : "memory");
                }
            }
        }
    }

    // ---- self-reset counters for the next graph replay ----
    __syncthreads();
    if (tid == 0) {
        int d = atomicAdd(&g_cnt[9], 1);
        if (d == (int)gridDim.x - 1) {
#pragma unroll
            for (int i = 0; i < 10; i++) g_cnt[i] = 0;
            __threadfence();
        }
    }
}

extern "C" void kernel_launch(void* const* d_in, const int* in_sizes, int n_in,
                              void* d_out, int out_size) {
    const float* x  = (const float*)d_in[0];
    const float* Wg = (const float*)d_in[1];
    const float* bg = (const float*)d_in[2];
    const float* We = (const float*)d_in[3];
    const float* be = (const float*)d_in[4];
    float* out = (float*)d_out;
    (void)in_sizes; (void)n_in; (void)out_size;

    cudaFuncSetAttribute(moe_gemm_kernel,
                         cudaFuncAttributeMaxDynamicSharedMemorySize, SMEM_TOTAL);

    prep_gate_kernel<<<5120, 256>>>((const float4*)We, (float4*)out, x, Wg, bg);
    moe_gemm_kernel<<<GRID_GEMM, 256, SMEM_TOTAL>>>(be, out);
}

// round 15
// speedup vs baseline: 1.1163x; 1.1163x over previous
#include <cuda_runtime.h>
#include <cuda_fp16.h>
#include <cstdint>
#include <cstddef>

#define T_TOK 8192
#define DM    1024
#define NE    8

#define BM 128
#define BN 256                    // full-tile N (mapping granularity)
#define CHUNK 64                  // halves of K per chunk (=128 B/row)
#define NCH (DM/CHUNK)            // 16
#define ABYTES (BM*128)           // 16384 per A stage
#define BBYTES (BN*128)           // 32768 per B stage (full size; halves use half)
#define A_OFF 4096
#define B_OFF (A_OFF + 3*ABYTES)
#define SMEM_TOTAL (B_OFF + 3*BBYTES)
#define GRID_GEMM 152

// ---- static device scratch (no allocations allowed) ----
__device__ __align__(16) __half g_x_h[(size_t)T_TOK * DM];     // fp16 x
__device__ __align__(16) __half g_We_h[(size_t)NE * DM * DM];  // fp16 We
__device__ int   g_tok[NE * T_TOK];
__device__ float g_wgt[NE * T_TOK];
__device__ int   g_cnt[16];   // [0..7]=counts, [8]=steal counter, [9]=done counter

__device__ __forceinline__ void cp16(uint32_t dst, const void* src) {
    asm volatile("cp.async.cg.shared.global [%0], [%1], 16;" :: "r"(dst), "l"(src) : "memory");
}

// ---- kernel 1: interleaved gate + prep (R11, unchanged) ----
__global__ void prep_gate_kernel(const float4* __restrict__ We, float4* __restrict__ out,
                                 const float* __restrict__ x, const float* __restrict__ Wg,
                                 const float* __restrict__ bg) {
    const int bid = blockIdx.x;
    const int tid = threadIdx.x;

    if (bid % 5 != 0) {
        int p = (bid / 5) * 4 + (bid % 5 - 1);       // 0..4095
        int i0 = p * 512 + tid;
        float4 w0 = We[i0];
        float4 w1 = We[i0 + 256];
        __half2 a0 = __floats2half2_rn(w0.x, w0.y);
        __half2 a1 = __floats2half2_rn(w0.z, w0.w);
        __half2 b0 = __floats2half2_rn(w1.x, w1.y);
        __half2 b1 = __floats2half2_rn(w1.z, w1.w);
        uint2 pk0, pk1;
        pk0.x = *reinterpret_cast<uint32_t*>(&a0);
        pk0.y = *reinterpret_cast<uint32_t*>(&a1);
        pk1.x = *reinterpret_cast<uint32_t*>(&b0);
        pk1.y = *reinterpret_cast<uint32_t*>(&b1);
        reinterpret_cast<uint2*>(g_We_h)[i0]       = pk0;
        reinterpret_cast<uint2*>(g_We_h)[i0 + 256] = pk1;
        out[i0]       = make_float4(0.f, 0.f, 0.f, 0.f);   // T_TOK*DM == NE*DM*DM
        out[i0 + 256] = make_float4(0.f, 0.f, 0.f, 0.f);
        return;
    }

    int t = (bid / 5) * 8 + (tid >> 5);
    int lane = tid & 31;
    const float4* xr4 = (const float4*)(x + (size_t)t * DM);
    uint2* xh2 = (uint2*)(g_x_h + (size_t)t * DM);

    float acc[NE];
#pragma unroll
    for (int e = 0; e < NE; e++) acc[e] = 0.f;

#pragma unroll
    for (int it = 0; it < DM / 4 / 32; it++) {
        int d4 = it * 32 + lane;
        float4 v = xr4[d4];
        __half2 h0 = __floats2half2_rn(v.x, v.y);
        __half2 h1 = __floats2half2_rn(v.z, v.w);
        uint2 pk;
        pk.x = *reinterpret_cast<uint32_t*>(&h0);
        pk.y = *reinterpret_cast<uint32_t*>(&h1);
        xh2[d4] = pk;
#pragma unroll
        for (int e = 0; e < NE; e++) {
            float4 g = ((const float4*)(Wg + e * DM))[d4];
            acc[e] = fmaf(v.x, g.x, acc[e]);
            acc[e] = fmaf(v.y, g.y, acc[e]);
            acc[e] = fmaf(v.z, g.z, acc[e]);
            acc[e] = fmaf(v.w, g.w, acc[e]);
        }
    }
#pragma unroll
    for (int e = 0; e < NE; e++) {
#pragma unroll
        for (int o = 16; o > 0; o >>= 1) acc[e] += __shfl_xor_sync(0xffffffffu, acc[e], o);
    }

    if (lane == 0) {
        float l[NE];
        float m = -1e30f;
#pragma unroll
        for (int e = 0; e < NE; e++) { l[e] = acc[e] + bg[e]; m = fmaxf(m, l[e]); }
        float p[NE];
        float s = 0.f;
#pragma unroll
        for (int e = 0; e < NE; e++) { p[e] = expf(l[e] - m); s += p[e]; }
        int e0 = 0;
#pragma unroll
        for (int e = 1; e < NE; e++) if (l[e] > l[e0]) e0 = e;
        int e1 = (e0 == 0) ? 1 : 0;
#pragma unroll
        for (int e = 0; e < NE; e++) if (e != e0 && l[e] > l[e1]) e1 = e;
        float inv = 1.f / s;

        int q0 = atomicAdd(&g_cnt[e0], 1);
        g_tok[e0 * T_TOK + q0] = t;
        g_wgt[e0 * T_TOK + q0] = p[e0] * inv;
        int q1 = atomicAdd(&g_cnt[e1], 1);
        g_tok[e1 * T_TOK + q1] = t;
        g_wgt[e1 * T_TOK + q1] = p[e1] * inv;
    }
}

// ---- tile body: FULL = 128x256 (warp 64x64), !FULL = 128x128 (warp 64x32) ----
template<bool FULL>
__device__ __forceinline__ void do_tile(int e, int m0, int n0, int cnt,
                                        const float* __restrict__ be,
                                        float* __restrict__ out,
                                        char* sm, uint32_t sbase) {
    constexpr int NA  = FULL ? 8 : 4;     // n-atoms (8-wide) per warp
    constexpr int NBG = FULL ? 8 : 4;     // B cp.async granules per thread
    constexpr int NWN = FULL ? 64 : 32;   // warp N width

    int*   s_tok  = (int*)sm;
    float* s_w    = (float*)(sm + 512);
    float* s_bias = (float*)(sm + 1024);

    const int tid = threadIdx.x;
    const int wid = tid >> 5, lane = tid & 31;
    const int wm = (wid & 1) * 64;
    const int wn = (wid >> 1) * NWN;
    const int gid = lane >> 2, tig = lane & 3;
    const uint32_t cmask = (uint32_t)((lane & 7) << 4);

    const uint32_t a_row = (uint32_t)(lane & 15);
    const uint32_t a_chi = (uint32_t)((lane >> 4) << 4);
    const uint32_t b_row = (uint32_t)(((lane >> 4) << 3) + (lane & 7));
    const uint32_t b_chi = (uint32_t)(((lane >> 3) & 1) << 4);

    if (tid < BM) {
        int pos = m0 + tid;
        int tok = 0; float wt = 0.f;
        if (pos < cnt) { tok = g_tok[e * T_TOK + pos]; wt = g_wgt[e * T_TOK + pos]; }
        s_tok[tid] = tok; s_w[tid] = wt;
    }
    if (FULL) s_bias[tid] = be[e * DM + n0 + tid];
    else if (tid >= BM) s_bias[tid - BM] = be[e * DM + n0 + (tid - BM)];
    __syncthreads();

    const __half* a_src[4];
    uint32_t a_dst[4];
#pragma unroll
    for (int i = 0; i < 4; i++) {
        int slot = i * 256 + tid;
        int row = slot >> 3, q = slot & 7;
        a_src[i] = g_x_h + (size_t)s_tok[row] * DM + q * 8;
        a_dst[i] = sbase + A_OFF + (uint32_t)(row * 128 + ((q ^ (row & 7)) << 4));
    }
    const __half* b_src[NBG];
    uint32_t b_dst[NBG];
#pragma unroll
    for (int i = 0; i < NBG; i++) {
        int slot = i * 256 + tid;
        int row = slot >> 3, q = slot & 7;
        b_src[i] = g_We_h + (size_t)e * DM * DM + (size_t)(n0 + row) * DM + q * 8;
        b_dst[i] = sbase + B_OFF + (uint32_t)(row * 128 + ((q ^ (row & 7)) << 4));
    }

    float acc[4][NA][4];
#pragma unroll
    for (int i0 = 0; i0 < 4; i0++)
#pragma unroll
        for (int i1 = 0; i1 < NA; i1++)
#pragma unroll
            for (int i2 = 0; i2 < 4; i2++) acc[i0][i1][i2] = 0.f;

#pragma unroll
    for (int ch = 0; ch < 2; ch++) {
        int k0 = ch * CHUNK;
#pragma unroll
        for (int i = 0; i < 4; i++) cp16(a_dst[i] + ch * ABYTES, a_src[i] + k0);
#pragma unroll
        for (int i = 0; i < NBG; i++) cp16(b_dst[i] + ch * BBYTES, b_src[i] + k0);
        asm volatile("cp.async.commit_group;" ::: "memory");
    }

    for (int ch = 0; ch < NCH; ++ch) {
        if (ch < NCH - 1) asm volatile("cp.async.wait_group 1;" ::: "memory");
        else              asm volatile("cp.async.wait_group 0;" ::: "memory");
        __syncthreads();

        const uint32_t Ab = sbase + A_OFF + (ch % 3) * ABYTES;
        const uint32_t Bb = sbase + B_OFF + (ch % 3) * BBYTES;

#pragma unroll
        for (int ks = 0; ks < 4; ks++) {
            uint32_t af[4][4];
#pragma unroll
            for (int ma = 0; ma < 4; ma++) {
                uint32_t cb = (uint32_t)(ks * 32) + a_chi;
                uint32_t addr = Ab + (wm + ma * 16 + a_row) * 128 + (cb ^ cmask);
                asm volatile("ldmatrix.sync.aligned.m8n8.x4.shared.b16 {%0,%1,%2,%3}, [%4];"
                             : "=r"(af[ma][0]), "=r"(af[ma][1]), "=r"(af[ma][2]), "=r"(af[ma][3])
                             : "r"(addr));
            }
            uint32_t bf[NA / 2][4];
#pragma unroll
            for (int nb2 = 0; nb2 < NA / 2; nb2++) {
                uint32_t cb = (uint32_t)(ks * 32) + b_chi;
                uint32_t addr = Bb + (wn + nb2 * 16 + b_row) * 128 + (cb ^ cmask);
                asm volatile("ldmatrix.sync.aligned.m8n8.x4.shared.b16 {%0,%1,%2,%3}, [%4];"
                             : "=r"(bf[nb2][0]), "=r"(bf[nb2][1]), "=r"(bf[nb2][2]), "=r"(bf[nb2][3])
                             : "r"(addr));
            }
#pragma unroll
            for (int ma = 0; ma < 4; ma++)
#pragma unroll
                for (int na = 0; na < NA; na++) {
                    uint32_t b0 = bf[na >> 1][(na & 1) * 2];
                    uint32_t b1 = bf[na >> 1][(na & 1) * 2 + 1];
                    asm volatile(
                        "mma.sync.aligned.m16n8k16.row.col.f32.f16.f16.f32 "
                        "{%0,%1,%2,%3}, {%4,%5,%6,%7}, {%8,%9}, {%0,%1,%2,%3};"
                        : "+f"(acc[ma][na][0]), "+f"(acc[ma][na][1]),
                          "+f"(acc[ma][na][2]), "+f"(acc[ma][na][3])
                        : "r"(af[ma][0]), "r"(af[ma][1]), "r"(af[ma][2]), "r"(af[ma][3]),
                          "r"(b0), "r"(b1));
                }

            if (ks == 0 && ch + 2 < NCH) {
                int st = (ch + 2) % 3;
                int k0 = (ch + 2) * CHUNK;
#pragma unroll
                for (int i = 0; i < 4; i++) cp16(a_dst[i] + st * ABYTES, a_src[i] + k0);
#pragma unroll
                for (int i = 0; i < NBG; i++) cp16(b_dst[i] + st * BBYTES, b_src[i] + k0);
                asm volatile("cp.async.commit_group;" ::: "memory");
            }
        }
    }

    // ---- epilogue ----
    const bool odd = (tig & 1);
#pragma unroll
    for (int ma = 0; ma < 4; ma++) {
        int r = wm + ma * 16 + gid;
        int rr = odd ? r + 8 : r;
        int tok = s_tok[rr];
        float wt = s_w[rr];
        float* orow = out + (size_t)tok * DM + n0;
#pragma unroll
        for (int na = 0; na < NA; na++) {
            float v0 = acc[ma][na][0], v1 = acc[ma][na][1];
            float v2 = acc[ma][na][2], v3 = acc[ma][na][3];
            float u0 = __shfl_xor_sync(0xffffffffu, v0, 1);
            float u1 = __shfl_xor_sync(0xffffffffu, v1, 1);
            float u2 = __shfl_xor_sync(0xffffffffu, v2, 1);
            float u3 = __shfl_xor_sync(0xffffffffu, v3, 1);
            float r0, r1, r2, r3;
            if (!odd) { r0 = v0; r1 = v1; r2 = u0; r3 = u1; }
            else      { r0 = u2; r1 = u3; r2 = v2; r3 = v3; }
            int j4 = wn + na * 8 + (tig >> 1) * 4;
            if (wt != 0.f) {
                float o0 = wt * (r0 + s_bias[j4 + 0]);
                float o1 = wt * (r1 + s_bias[j4 + 1]);
                float o2 = wt * (r2 + s_bias[j4 + 2]);
                float o3 = wt * (r3 + s_bias[j4 + 3]);
                asm volatile("red.global.add.v4.f32 [%0], {%1,%2,%3,%4};"
                             :: "l"(orow + j4), "f"(o0), "f"(o1), "f"(o2), "f"(o3)
                             : "memory");
            }
        }
    }
}

// ---- kernel 2: persistent stealing GEMM with last-wave N-splitting ----
__global__ void __launch_bounds__(256, 1)
moe_gemm_kernel(const float* __restrict__ be, float* __restrict__ out) {
    extern __shared__ __align__(1024) char sm[];
    int* s_wid = (int*)(sm + 2048);
    int* s_cnt = (int*)(sm + 2064);        // 8 ints

    const int tid = threadIdx.x;
    const uint32_t sbase = (uint32_t)__cvta_generic_to_shared(sm);

    if (tid < 8) s_cnt[tid] = g_cnt[tid];

    for (;;) {
        if (tid == 0) *s_wid = atomicAdd(&g_cnt[8], 1);
        __syncthreads();                   // publish s_wid/s_cnt; prev epilogue done
        const int w = *s_wid;

        // items per expert (full 128x256 tiles), total Q, split point S
        int itc[NE], mbec[NE];
        int Q = 0;
#pragma unroll
        for (int ee = 0; ee < NE; ee++) {
            int mbe = (s_cnt[ee] + BM - 1) >> 7;
            mbec[ee] = mbe;
            itc[ee] = mbe * (DM / BN);
            Q += itc[ee];
        }
        const int S = (Q / GRID_GEMM) * GRID_GEMM;   // ids < S: full tiles
        int i, nh = -1;
        if (w < S) {
            i = w;
        } else {
            int h = w - S;
            if (h >= 2 * (Q - S)) break;   // queue drained
            i = S + (h >> 1);
            nh = h & 1;                    // which 128-wide half
        }

        // map item i -> (e, nb, mb); m innermost
        int rem = i, e = -1, mb = 0, nb = 0;
#pragma unroll
        for (int ee = 0; ee < NE; ee++) {
            if (e < 0) {
                if (rem < itc[ee]) { e = ee; nb = rem / mbec[ee]; mb = rem - nb * mbec[ee]; }
                else rem -= itc[ee];
            }
        }

        const int cnt = s_cnt[e];
        const int m0 = mb * BM;
        const int n0 = nb * BN + (nh == 1 ? 128 : 0);

        if (nh < 0) do_tile<true >(e, m0, n0, cnt, be, out, sm, sbase);
        else        do_tile<false>(e, m0, n0, cnt, be, out, sm, sbase);
    }

    // ---- self-reset counters for the next graph replay ----
    __syncthreads();
    if (tid == 0) {
        int d = atomicAdd(&g_cnt[9], 1);
        if (d == (int)gridDim.x - 1) {
#pragma unroll
            for (int i = 0; i < 10; i++) g_cnt[i] = 0;
            __threadfence();
        }
    }
}

extern "C" void kernel_launch(void* const* d_in, const int* in_sizes, int n_in,
                              void* d_out, int out_size) {
    const float* x  = (const float*)d_in[0];
    const float* Wg = (const float*)d_in[1];
    const float* bg = (const float*)d_in[2];
    const float* We = (const float*)d_in[3];
    const float* be = (const float*)d_in[4];
    float* out = (float*)d_out;
    (void)in_sizes; (void)n_in; (void)out_size;

    cudaFuncSetAttribute(moe_gemm_kernel,
                         cudaFuncAttributeMaxDynamicSharedMemorySize, SMEM_TOTAL);

    prep_gate_kernel<<<5120, 256>>>((const float4*)We, (float4*)out, x, Wg, bg);
    moe_gemm_kernel<<<GRID_GEMM, 256, SMEM_TOTAL>>>(be, out);
}

// round 16
// speedup vs baseline: 1.1230x; 1.0060x over previous
#include <cuda_runtime.h>
#include <cuda_fp16.h>
#include <cstdint>
#include <cstddef>

#define T_TOK 8192
#define DM    1024
#define NE    8

#define BM 128
#define BN 256                    // full-tile N (mapping granularity)
#define CHUNK 64                  // halves of K per chunk (=128 B/row)
#define NCH (DM/CHUNK)            // 16
#define NSTG 4                    // cp.async pipeline stages
#define ABYTES (BM*128)           // 16384 per A stage
#define BBYTES (BN*128)           // 32768 per B stage (full size; halves use half)
#define A_OFF 4096
#define B_OFF (A_OFF + NSTG*ABYTES)
#define SMEM_TOTAL (B_OFF + NSTG*BBYTES)     // 200704
#define GRID_GEMM 152

// ---- static device scratch (no allocations allowed) ----
__device__ __align__(16) __half g_x_h[(size_t)T_TOK * DM];     // fp16 x
__device__ __align__(16) __half g_We_h[(size_t)NE * DM * DM];  // fp16 We
__device__ int   g_tok[NE * T_TOK];
__device__ float g_wgt[NE * T_TOK];
__device__ int   g_cnt[16];   // [0..7]=counts, [8]=steal counter, [9]=done counter

__device__ __forceinline__ void cp16(uint32_t dst, const void* src) {
    asm volatile("cp.async.cg.shared.global [%0], [%1], 16;" :: "r"(dst), "l"(src) : "memory");
}

// ---- kernel 1: interleaved gate + prep (R11, unchanged) ----
__global__ void prep_gate_kernel(const float4* __restrict__ We, float4* __restrict__ out,
                                 const float* __restrict__ x, const float* __restrict__ Wg,
                                 const float* __restrict__ bg) {
    const int bid = blockIdx.x;
    const int tid = threadIdx.x;

    if (bid % 5 != 0) {
        int p = (bid / 5) * 4 + (bid % 5 - 1);       // 0..4095
        int i0 = p * 512 + tid;
        float4 w0 = We[i0];
        float4 w1 = We[i0 + 256];
        __half2 a0 = __floats2half2_rn(w0.x, w0.y);
        __half2 a1 = __floats2half2_rn(w0.z, w0.w);
        __half2 b0 = __floats2half2_rn(w1.x, w1.y);
        __half2 b1 = __floats2half2_rn(w1.z, w1.w);
        uint2 pk0, pk1;
        pk0.x = *reinterpret_cast<uint32_t*>(&a0);
        pk0.y = *reinterpret_cast<uint32_t*>(&a1);
        pk1.x = *reinterpret_cast<uint32_t*>(&b0);
        pk1.y = *reinterpret_cast<uint32_t*>(&b1);
        reinterpret_cast<uint2*>(g_We_h)[i0]       = pk0;
        reinterpret_cast<uint2*>(g_We_h)[i0 + 256] = pk1;
        out[i0]       = make_float4(0.f, 0.f, 0.f, 0.f);   // T_TOK*DM == NE*DM*DM
        out[i0 + 256] = make_float4(0.f, 0.f, 0.f, 0.f);
        return;
    }

    int t = (bid / 5) * 8 + (tid >> 5);
    int lane = tid & 31;
    const float4* xr4 = (const float4*)(x + (size_t)t * DM);
    uint2* xh2 = (uint2*)(g_x_h + (size_t)t * DM);

    float acc[NE];
#pragma unroll
    for (int e = 0; e < NE; e++) acc[e] = 0.f;

#pragma unroll
    for (int it = 0; it < DM / 4 / 32; it++) {
        int d4 = it * 32 + lane;
        float4 v = xr4[d4];
        __half2 h0 = __floats2half2_rn(v.x, v.y);
        __half2 h1 = __floats2half2_rn(v.z, v.w);
        uint2 pk;
        pk.x = *reinterpret_cast<uint32_t*>(&h0);
        pk.y = *reinterpret_cast<uint32_t*>(&h1);
        xh2[d4] = pk;
#pragma unroll
        for (int e = 0; e < NE; e++) {
            float4 g = ((const float4*)(Wg + e * DM))[d4];
            acc[e] = fmaf(v.x, g.x, acc[e]);
            acc[e] = fmaf(v.y, g.y, acc[e]);
            acc[e] = fmaf(v.z, g.z, acc[e]);
            acc[e] = fmaf(v.w, g.w, acc[e]);
        }
    }
#pragma unroll
    for (int e = 0; e < NE; e++) {
#pragma unroll
        for (int o = 16; o > 0; o >>= 1) acc[e] += __shfl_xor_sync(0xffffffffu, acc[e], o);
    }

    if (lane == 0) {
        float l[NE];
        float m = -1e30f;
#pragma unroll
        for (int e = 0; e < NE; e++) { l[e] = acc[e] + bg[e]; m = fmaxf(m, l[e]); }
        float p[NE];
        float s = 0.f;
#pragma unroll
        for (int e = 0; e < NE; e++) { p[e] = expf(l[e] - m); s += p[e]; }
        int e0 = 0;
#pragma unroll
        for (int e = 1; e < NE; e++) if (l[e] > l[e0]) e0 = e;
        int e1 = (e0 == 0) ? 1 : 0;
#pragma unroll
        for (int e = 0; e < NE; e++) if (e != e0 && l[e] > l[e1]) e1 = e;
        float inv = 1.f / s;

        int q0 = atomicAdd(&g_cnt[e0], 1);
        g_tok[e0 * T_TOK + q0] = t;
        g_wgt[e0 * T_TOK + q0] = p[e0] * inv;
        int q1 = atomicAdd(&g_cnt[e1], 1);
        g_tok[e1 * T_TOK + q1] = t;
        g_wgt[e1 * T_TOK + q1] = p[e1] * inv;
    }
}

// ---- tile body: FULL = 128x256 (warp 64x64), !FULL = 128x128 (warp 64x32) ----
template<bool FULL>
__device__ __forceinline__ void do_tile(int e, int m0, int n0, int cnt,
                                        const float* __restrict__ be,
                                        float* __restrict__ out,
                                        char* sm, uint32_t sbase) {
    constexpr int NA  = FULL ? 8 : 4;     // n-atoms (8-wide) per warp
    constexpr int NBG = FULL ? 8 : 4;     // B cp.async granules per thread
    constexpr int NWN = FULL ? 64 : 32;   // warp N width

    int*   s_tok  = (int*)sm;
    float* s_w    = (float*)(sm + 512);
    float* s_bias = (float*)(sm + 1024);

    const int tid = threadIdx.x;
    const int wid = tid >> 5, lane = tid & 31;
    const int wm = (wid & 1) * 64;
    const int wn = (wid >> 1) * NWN;
    const int gid = lane >> 2, tig = lane & 3;
    const uint32_t cmask = (uint32_t)((lane & 7) << 4);

    const uint32_t a_row = (uint32_t)(lane & 15);
    const uint32_t a_chi = (uint32_t)((lane >> 4) << 4);
    const uint32_t b_row = (uint32_t)(((lane >> 4) << 3) + (lane & 7));
    const uint32_t b_chi = (uint32_t)(((lane >> 3) & 1) << 4);

    if (tid < BM) {
        int pos = m0 + tid;
        int tok = 0; float wt = 0.f;
        if (pos < cnt) { tok = g_tok[e * T_TOK + pos]; wt = g_wgt[e * T_TOK + pos]; }
        s_tok[tid] = tok; s_w[tid] = wt;
    }
    if (FULL) s_bias[tid] = be[e * DM + n0 + tid];
    else if (tid >= BM) s_bias[tid - BM] = be[e * DM + n0 + (tid - BM)];
    __syncthreads();

    const __half* a_src[4];
    uint32_t a_dst[4];
#pragma unroll
    for (int i = 0; i < 4; i++) {
        int slot = i * 256 + tid;
        int row = slot >> 3, q = slot & 7;
        a_src[i] = g_x_h + (size_t)s_tok[row] * DM + q * 8;
        a_dst[i] = sbase + A_OFF + (uint32_t)(row * 128 + ((q ^ (row & 7)) << 4));
    }
    const __half* b_src[NBG];
    uint32_t b_dst[NBG];
#pragma unroll
    for (int i = 0; i < NBG; i++) {
        int slot = i * 256 + tid;
        int row = slot >> 3, q = slot & 7;
        b_src[i] = g_We_h + (size_t)e * DM * DM + (size_t)(n0 + row) * DM + q * 8;
        b_dst[i] = sbase + B_OFF + (uint32_t)(row * 128 + ((q ^ (row & 7)) << 4));
    }

    float acc[4][NA][4];
#pragma unroll
    for (int i0 = 0; i0 < 4; i0++)
#pragma unroll
        for (int i1 = 0; i1 < NA; i1++)
#pragma unroll
            for (int i2 = 0; i2 < 4; i2++) acc[i0][i1][i2] = 0.f;

    // prologue: chunks 0..2 -> stages 0..2 (3 groups in flight)
#pragma unroll
    for (int ch = 0; ch < NSTG - 1; ch++) {
        int k0 = ch * CHUNK;
#pragma unroll
        for (int i = 0; i < 4; i++) cp16(a_dst[i] + ch * ABYTES, a_src[i] + k0);
#pragma unroll
        for (int i = 0; i < NBG; i++) cp16(b_dst[i] + ch * BBYTES, b_src[i] + k0);
        asm volatile("cp.async.commit_group;" ::: "memory");
    }

    for (int ch = 0; ch < NCH; ++ch) {
        if (ch < NCH - 2)      asm volatile("cp.async.wait_group 2;" ::: "memory");
        else if (ch < NCH - 1) asm volatile("cp.async.wait_group 1;" ::: "memory");
        else                   asm volatile("cp.async.wait_group 0;" ::: "memory");
        __syncthreads();

        const uint32_t Ab = sbase + A_OFF + (ch % NSTG) * ABYTES;
        const uint32_t Bb = sbase + B_OFF + (ch % NSTG) * BBYTES;

#pragma unroll
        for (int ks = 0; ks < 4; ks++) {
            uint32_t af[4][4];
#pragma unroll
            for (int ma = 0; ma < 4; ma++) {
                uint32_t cb = (uint32_t)(ks * 32) + a_chi;
                uint32_t addr = Ab + (wm + ma * 16 + a_row) * 128 + (cb ^ cmask);
                asm volatile("ldmatrix.sync.aligned.m8n8.x4.shared.b16 {%0,%1,%2,%3}, [%4];"
                             : "=r"(af[ma][0]), "=r"(af[ma][1]), "=r"(af[ma][2]), "=r"(af[ma][3])
                             : "r"(addr));
            }
            uint32_t bf[NA / 2][4];
#pragma unroll
            for (int nb2 = 0; nb2 < NA / 2; nb2++) {
                uint32_t cb = (uint32_t)(ks * 32) + b_chi;
                uint32_t addr = Bb + (wn + nb2 * 16 + b_row) * 128 + (cb ^ cmask);
                asm volatile("ldmatrix.sync.aligned.m8n8.x4.shared.b16 {%0,%1,%2,%3}, [%4];"
                             : "=r"(bf[nb2][0]), "=r"(bf[nb2][1]), "=r"(bf[nb2][2]), "=r"(bf[nb2][3])
                             : "r"(addr));
            }
#pragma unroll
            for (int ma = 0; ma < 4; ma++)
#pragma unroll
                for (int na = 0; na < NA; na++) {
                    uint32_t b0 = bf[na >> 1][(na & 1) * 2];
                    uint32_t b1 = bf[na >> 1][(na & 1) * 2 + 1];
                    asm volatile(
                        "mma.sync.aligned.m16n8k16.row.col.f32.f16.f16.f32 "
                        "{%0,%1,%2,%3}, {%4,%5,%6,%7}, {%8,%9}, {%0,%1,%2,%3};"
                        : "+f"(acc[ma][na][0]), "+f"(acc[ma][na][1]),
                          "+f"(acc[ma][na][2]), "+f"(acc[ma][na][3])
                        : "r"(af[ma][0]), "r"(af[ma][1]), "r"(af[ma][2]), "r"(af[ma][3]),
                          "r"(b0), "r"(b1));
                }

            if (ks == 0 && ch + NSTG - 1 < NCH) {
                int st = (ch + NSTG - 1) % NSTG;
                int k0 = (ch + NSTG - 1) * CHUNK;
#pragma unroll
                for (int i = 0; i < 4; i++) cp16(a_dst[i] + st * ABYTES, a_src[i] + k0);
#pragma unroll
                for (int i = 0; i < NBG; i++) cp16(b_dst[i] + st * BBYTES, b_src[i] + k0);
                asm volatile("cp.async.commit_group;" ::: "memory");
            }
        }
    }

    // ---- epilogue ----
    const bool odd = (tig & 1);
#pragma unroll
    for (int ma = 0; ma < 4; ma++) {
        int r = wm + ma * 16 + gid;
        int rr = odd ? r + 8 : r;
        int tok = s_tok[rr];
        float wt = s_w[rr];
        float* orow = out + (size_t)tok * DM + n0;
#pragma unroll
        for (int na = 0; na < NA; na++) {
            float v0 = acc[ma][na][0], v1 = acc[ma][na][1];
            float v2 = acc[ma][na][2], v3 = acc[ma][na][3];
            float u0 = __shfl_xor_sync(0xffffffffu, v0, 1);
            float u1 = __shfl_xor_sync(0xffffffffu, v1, 1);
            float u2 = __shfl_xor_sync(0xffffffffu, v2, 1);
            float u3 = __shfl_xor_sync(0xffffffffu, v3, 1);
            float r0, r1, r2, r3;
            if (!odd) { r0 = v0; r1 = v1; r2 = u0; r3 = u1; }
            else      { r0 = u2; r1 = u3; r2 = v2; r3 = v3; }
            int j4 = wn + na * 8 + (tig >> 1) * 4;
            if (wt != 0.f) {
                float o0 = wt * (r0 + s_bias[j4 + 0]);
                float o1 = wt * (r1 + s_bias[j4 + 1]);
                float o2 = wt * (r2 + s_bias[j4 + 2]);
                float o3 = wt * (r3 + s_bias[j4 + 3]);
                asm volatile("red.global.add.v4.f32 [%0], {%1,%2,%3,%4};"
                             :: "l"(orow + j4), "f"(o0), "f"(o1), "f"(o2), "f"(o3)
                             : "memory");
            }
        }
    }
}

// ---- kernel 2: persistent stealing GEMM with last-wave N-splitting ----
__global__ void __launch_bounds__(256, 1)
moe_gemm_kernel(const float* __restrict__ be, float* __restrict__ out) {
    extern __shared__ __align__(1024) char sm[];
    int* s_wid = (int*)(sm + 2048);
    int* s_cnt = (int*)(sm + 2064);        // 8 ints

    const int tid = threadIdx.x;
    const uint32_t sbase = (uint32_t)__cvta_generic_to_shared(sm);

    if (tid < 8) s_cnt[tid] = g_cnt[tid];

    for (;;) {
        if (tid == 0) *s_wid = atomicAdd(&g_cnt[8], 1);
        __syncthreads();                   // publish s_wid/s_cnt; prev epilogue done
        const int w = *s_wid;

        // items per expert (full 128x256 tiles), total Q, split point S
        int itc[NE], mbec[NE];
        int Q = 0;
#pragma unroll
        for (int ee = 0; ee < NE; ee++) {
            int mbe = (s_cnt[ee] + BM - 1) >> 7;
            mbec[ee] = mbe;
            itc[ee] = mbe * (DM / BN);
            Q += itc[ee];
        }
        const int S = (Q / GRID_GEMM) * GRID_GEMM;   // ids < S: full tiles
        int i, nh = -1;
        if (w < S) {
            i = w;
        } else {
            int h = w - S;
            if (h >= 2 * (Q - S)) break;   // queue drained
            i = S + (h >> 1);
            nh = h & 1;                    // which 128-wide half
        }

        // map item i -> (e, nb, mb); m innermost
        int rem = i, e = -1, mb = 0, nb = 0;
#pragma unroll
        for (int ee = 0; ee < NE; ee++) {
            if (e < 0) {
                if (rem < itc[ee]) { e = ee; nb = rem / mbec[ee]; mb = rem - nb * mbec[ee]; }
                else rem -= itc[ee];
            }
        }

        const int cnt = s_cnt[e];
        const int m0 = mb * BM;
        const int n0 = nb * BN + (nh == 1 ? 128 : 0);

        if (nh < 0) do_tile<true >(e, m0, n0, cnt, be, out, sm, sbase);
        else        do_tile<false>(e, m0, n0, cnt, be, out, sm, sbase);
    }

    // ---- self-reset counters for the next graph replay ----
    __syncthreads();
    if (tid == 0) {
        int d = atomicAdd(&g_cnt[9], 1);
        if (d == (int)gridDim.x - 1) {
#pragma unroll
            for (int i = 0; i < 10; i++) g_cnt[i] = 0;
            __threadfence();
        }
    }
}

extern "C" void kernel_launch(void* const* d_in, const int* in_sizes, int n_in,
                              void* d_out, int out_size) {
    const float* x  = (const float*)d_in[0];
    const float* Wg = (const float*)d_in[1];
    const float* bg = (const float*)d_in[2];
    const float* We = (const float*)d_in[3];
    const float* be = (const float*)d_in[4];
    float* out = (float*)d_out;
    (void)in_sizes; (void)n_in; (void)out_size;

    cudaFuncSetAttribute(moe_gemm_kernel,
                         cudaFuncAttributeMaxDynamicSharedMemorySize, SMEM_TOTAL);

    prep_gate_kernel<<<5120, 256>>>((const float4*)We, (float4*)out, x, Wg, bg);
    moe_gemm_kernel<<<GRID_GEMM, 256, SMEM_TOTAL>>>(be, out);
}